// round 16
// baseline (speedup 1.0000x reference)
#include <cuda_runtime.h>
#include <math.h>

typedef unsigned long long ull;

#define NB 16
#define HP 256
#define HW 65536
#define NTOT (NB*HW)

// g_scal layout
#define GAM   0
#define DEL   110
#define ALF   220
#define BBIDX 330
#define ATOL2 331

// ---------------- static device scratch ----------------
__device__ float  g_h1[(size_t)NB*32*HW];   // variance hidden
__device__ float  g_h2[(size_t)NB*32*HW];   // g-features
__device__ float  g_h3[(size_t)NB*32*HW];   // s-features
__device__ float2 g_w2[NTOT];               // (wv, wh) packed
__device__ float4 g_RWS0[NTOT];             // (r, w=Ar, s, p) ping
__device__ float4 g_RWS1[NTOT];             // pong
__device__ float  g_scal[512];

// conv weights in constant memory (uniform-path loads, off the LDS crossbar)
__constant__ float c_w2t[9216];
__constant__ float c_w1t[1152];

// ---------------- f32x2 helpers ----------------
__device__ __forceinline__ ull pack2(float a, float b){ ull r; asm("mov.b64 %0, {%1, %2};" : "=l"(r) : "f"(a), "f"(b)); return r; }
__device__ __forceinline__ void ffma2(ull& d, ull a, ull b){ asm("fma.rn.f32x2 %0, %1, %2, %0;" : "+l"(d) : "l"(a), "l"(b)); }
__device__ __forceinline__ float2 unpack2(ull v){ float2 f; asm("mov.b64 {%0, %1}, %2;" : "=f"(f.x), "=f"(f.y) : "l"(v)); return f; }

__global__ void zero_scal_kernel(){ g_scal[threadIdx.x] = 0.f; g_scal[256+threadIdx.x] = 0.f; }

// transpose conv weights OIHW -> [(ci*9+tap)*32+co] into gmem staging buffers
__device__ float g_w2t_stage[9216];
__device__ float g_w1t_stage[1152];
__global__ void transpose_w2_kernel(const float* __restrict__ W2){
  int idx = blockIdx.x*256 + threadIdx.x;
  if (idx < 9216){
    int co = idx & 31; int ct = idx >> 5;
    int ci = ct/9, tap = ct - ci*9;
    g_w2t_stage[idx] = W2[((size_t)co*32 + ci)*9 + tap];
  }
}
__global__ void transpose_w1_kernel(const float* __restrict__ W1, int cin){
  int idx = blockIdx.x*256 + threadIdx.x;
  if (idx < cin*9*32){
    int co = idx & 31; int ct = idx >> 5;
    int ci = ct/9, tap = ct - ci*9;
    g_w1t_stage[idx] = W1[((size_t)co*cin + ci)*9 + tap];
  }
}

// =====================================================================
// FUSED conv1(CIN->32, relu) + conv2(32->32, RELU2), 16x16 tile.
// Both weight sets in __constant__; smem only for data. 4 blocks/SM.
// conv1 computed in two 16-channel halves to keep regs <= 64.
// =====================================================================
template<int CINA,int CINB,bool RELU2>
__global__ void __launch_bounds__(256,4) conv3x3_fused2(
    const float* __restrict__ inA, const float* __restrict__ inB,
    const float* __restrict__ b1, const float* __restrict__ b2,
    float* __restrict__ out)
{
  constexpr int CIN = CINA + CINB;
  extern __shared__ float sm[];
  float* s_in = sm;                       // CIN*20*21
  float* s_h  = s_in + CIN*20*21;         // 32*18*20

  const int tid = threadIdx.x;
  const int b   = blockIdx.z;
  const int tx0 = blockIdx.x*16, ty0 = blockIdx.y*16;

  for (int idx = tid; idx < CIN*400; idx += 256){
    int ci = idx/400; int rem = idx - ci*400;
    int r = rem/20, c2 = rem - r*20;
    int gy = ty0 + r - 2, gx = tx0 + c2 - 2;
    const float* src = (ci < CINA) ? (inA + ((size_t)b*CINA + ci)*HW)
                                   : (inB + ((size_t)b*CINB + (ci-CINA))*HW);
    float v = 0.f;
    if (gy >= 0 && gy < HP && gx >= 0 && gx < HP) v = src[gy*HP+gx];
    s_in[(ci*20 + r)*21 + c2] = v;
  }
  __syncthreads();

  // ---- conv1 + relu -> s_h on 18x18 halo (two halves of 16 channels) ----
  for (int p = tid; p < 324; p += 256){
    int yy = p/18, xx = p - yy*18;
    int gy = ty0 + yy - 1, gx = tx0 + xx - 1;
    if (gy < 0 || gy >= HP || gx < 0 || gx >= HP){
      #pragma unroll
      for (int co = 0; co < 32; co++) s_h[(co*18 + yy)*20 + xx] = 0.f;
    } else {
      #pragma unroll
      for (int h = 0; h < 2; h++){
        ull acc[8];
        #pragma unroll
        for (int q = 0; q < 8; q++){
          int co0 = 16*h + 2*q;
          acc[q] = pack2(__ldg(&b1[co0]), __ldg(&b1[co0+1]));
        }
        #pragma unroll
        for (int ci = 0; ci < CIN; ci++){
          #pragma unroll
          for (int ky = 0; ky < 3; ky++)
            #pragma unroll
            for (int kx = 0; kx < 3; kx++){
              float v = s_in[(ci*20 + yy + ky)*21 + xx + kx];
              ull vv = pack2(v, v);
              const ull* wp = reinterpret_cast<const ull*>(c_w1t + (ci*9 + ky*3 + kx)*32) + h*8;
              #pragma unroll
              for (int q = 0; q < 8; q++) ffma2(acc[q], vv, wp[q]);
            }
        }
        #pragma unroll
        for (int q = 0; q < 8; q++){
          float2 a = unpack2(acc[q]);
          a.x = fmaxf(a.x, 0.f); a.y = fmaxf(a.y, 0.f);
          int co0 = 16*h + 2*q;
          s_h[((co0  )*18 + yy)*20 + xx] = a.x;
          s_h[((co0+1)*18 + yy)*20 + xx] = a.y;
        }
      }
    }
  }
  __syncthreads();

  // ---- conv2 from smem inputs + constant weights (register-dieted) ----
  const int cog  = tid >> 6;
  const int slot = tid & 63;
  const int px   = slot & 15;
  const int py   = (slot >> 4) << 2;

  ull acc[4][4];
  #pragma unroll
  for (int q = 0; q < 4; q++){
    int co0 = 2*(cog*4 + q);
    ull bz = pack2(__ldg(&b2[co0]), __ldg(&b2[co0+1]));
    #pragma unroll
    for (int pix = 0; pix < 4; pix++) acc[pix][q] = bz;
  }

  #pragma unroll 1
  for (int cl = 0; cl < 32; cl++){
    float v[6][3];
    #pragma unroll
    for (int dy = 0; dy < 6; dy++)
      #pragma unroll
      for (int dx = 0; dx < 3; dx++)
        v[dy][dx] = s_h[(cl*18 + py + dy)*20 + px + dx];
    #pragma unroll
    for (int ky = 0; ky < 3; ky++)
      #pragma unroll
      for (int kx = 0; kx < 3; kx++){
        ull vv0 = pack2(v[ky  ][kx], v[ky  ][kx]);
        ull vv1 = pack2(v[ky+1][kx], v[ky+1][kx]);
        ull vv2 = pack2(v[ky+2][kx], v[ky+2][kx]);
        ull vv3 = pack2(v[ky+3][kx], v[ky+3][kx]);
        const ull* wp = reinterpret_cast<const ull*>(c_w2t + (cl*9 + ky*3 + kx)*32) + cog*4;
        #pragma unroll
        for (int q = 0; q < 4; q++){
          ull w = wp[q];
          ffma2(acc[0][q], vv0, w);
          ffma2(acc[1][q], vv1, w);
          ffma2(acc[2][q], vv2, w);
          ffma2(acc[3][q], vv3, w);
        }
      }
  }

  #pragma unroll
  for (int q = 0; q < 4; q++){
    int co0 = 2*(cog*4 + q);
    #pragma unroll
    for (int pix = 0; pix < 4; pix++){
      float2 a = unpack2(acc[pix][q]);
      if (RELU2){ a.x = fmaxf(a.x, 0.f); a.y = fmaxf(a.y, 0.f); }
      size_t o = ((size_t)b*32 + co0)*HW + (size_t)(ty0+py+pix)*HP + (tx0+px);
      out[o] = a.x; out[o + HW] = a.y;
    }
  }
}

// conv 32 -> 1 (variance head)
__global__ void __launch_bounds__(256) conv3x3_one(
    const float* __restrict__ in, const float* __restrict__ W,
    const float* __restrict__ bias, float* __restrict__ out)
{
  __shared__ float s_in[8][34][36];
  __shared__ float s_w[8*9];
  const int tid = threadIdx.x;
  const int px = tid & 31;
  const int py = (tid >> 5) << 2;
  const int b = blockIdx.z;
  const int tx0 = blockIdx.x*32, ty0 = blockIdx.y*32;

  float acc[4];
  float bz = __ldg(&bias[0]);
  #pragma unroll
  for (int pix = 0; pix < 4; pix++) acc[pix] = bz;

  #pragma unroll 1
  for (int c0 = 0; c0 < 32; c0 += 8){
    if (c0) __syncthreads();
    if (tid < 72) s_w[tid] = W[c0*9 + tid];
    for (int idx = tid; idx < 8*1156; idx += 256){
      int cl = idx/1156; int rem = idx - cl*1156;
      int yy = rem/34, xx = rem - yy*34;
      int gy = ty0+yy-1, gx = tx0+xx-1;
      float v = 0.f;
      if (gy >= 0 && gy < HP && gx >= 0 && gx < HP)
        v = in[((size_t)b*32 + c0+cl)*HW + gy*HP + gx];
      s_in[cl][yy][xx] = v;
    }
    __syncthreads();
    #pragma unroll 1
    for (int cl = 0; cl < 8; cl++){
      float v[6][3];
      #pragma unroll
      for (int dy = 0; dy < 6; dy++)
        #pragma unroll
        for (int dx = 0; dx < 3; dx++) v[dy][dx] = s_in[cl][py+dy][px+dx];
      #pragma unroll
      for (int ky = 0; ky < 3; ky++)
        #pragma unroll
        for (int kx = 0; kx < 3; kx++){
          float w = s_w[cl*9 + ky*3 + kx];
          #pragma unroll
          for (int pix = 0; pix < 4; pix++) acc[pix] += v[pix+ky][kx]*w;
        }
    }
  }
  #pragma unroll
  for (int pix = 0; pix < 4; pix++)
    out[(size_t)b*HW + (size_t)(ty0+py+pix)*HP + (tx0+px)] = acc[pix];
}

// ---------------- affinity (smem-tiled), writes packed float2 (wv,wh) ----------------
__global__ void __launch_bounds__(256) affinity_kernel(const float* __restrict__ logmu){
  __shared__ float sg[33][36], ss[33][36];
  const int b = blockIdx.z, tx0 = blockIdx.x*32, ty0 = blockIdx.y*32;
  const float mu = expf(logmu[0]);
  const int px = threadIdx.x & 31, py = (threadIdx.x >> 5) << 2;
  float dv[4] = {0,0,0,0}, dh[4] = {0,0,0,0};
  const float* gb = g_h2 + (size_t)b*32*HW;
  const float* sb = g_h3 + (size_t)b*32*HW;

  #pragma unroll 1
  for (int c = 0; c < 32; c++){
    __syncthreads();
    for (int idx = threadIdx.x; idx < 33*33; idx += 256){
      int yy = idx/33, xx = idx - yy*33;
      int gy = ty0+yy, gx = tx0+xx;
      float vg = 0.f, vs = 0.f;
      if (gy < HP && gx < HP){
        size_t o = (size_t)c*HW + gy*HP + gx;
        vg = gb[o]; vs = sb[o];
      }
      sg[yy][xx] = vg; ss[yy][xx] = vs;
    }
    __syncthreads();
    #pragma unroll
    for (int k = 0; k < 4; k++){
      int y = py + k;
      float a  = sg[y][px], a2 = ss[y][px];
      float d;
      d = sg[y+1][px]   - a;  dv[k] += d*d;
      d = ss[y+1][px]   - a2; dv[k] += d*d;
      d = sg[y][px+1]   - a;  dh[k] += d*d;
      d = ss[y][px+1]   - a2; dh[k] += d*d;
    }
  }
  #pragma unroll
  for (int k = 0; k < 4; k++){
    int gi = ty0+py+k, gj = tx0+px;
    int idx = (b*HP + gi)*HP + gj;
    float wv = (gi < 255) ? expf(-mu*dv[k]) : 0.f;
    float wh = (gj < 255) ? expf(-mu*dh[k]) : 0.f;
    g_w2[idx] = make_float2(wv, wh);
  }
}

// ---------------- assemble aff output (B,5,H,W) ----------------
__global__ void __launch_bounds__(256) assemble_kernel(float* __restrict__ aff, const float* __restrict__ loglam){
  int idx = blockIdx.x*256 + threadIdx.x;
  int b = idx >> 16, rem = idx & 65535, i = rem >> 8, j = rem & 255;
  float lam = expf(loglam[0]);
  float2 c = g_w2[idx];
  float wdn = c.x, wrt = c.y;
  float wup = (i > 0) ? g_w2[idx-HP].x : 0.f;
  float wlf = (j > 0) ? g_w2[idx-1].y  : 0.f;
  float* o = aff + (size_t)b*5*HW + rem;
  o[0]            = wup;
  o[HW]           = wdn;
  o[(size_t)2*HW] = wlf;
  o[(size_t)3*HW] = wrt;
  o[(size_t)4*HW] = wup + wdn + wlf + wrt + lam;
}

// ======================= CG on 32x32 tiles, float4 (r,w,s,p) =======================
template<bool WS>
__device__ __forceinline__ void matvec_phase2(
    float sp[34][36], const float ssrc[34][36], const float psrc[34][36],
    float lam, const float* __restrict__ mask,
    int b, int tx0, int ty0, float4* __restrict__ Out_b, int i1, int i2)
{
  __shared__ float scell[4][4];
  __shared__ float sred[8], sred2[8];
  const int tid = threadIdx.x;
  if (tid < 16) ((float*)scell)[tid] = 0.f;
  __syncthreads();

  const int col = tid & 31, rb_ = tid >> 5;
  float pc[4], lap[4];
  #pragma unroll
  for (int kk = 0; kk < 4; kk++){
    int rr = rb_ + 8*kk;
    int gi = ty0 + rr, gj = tx0 + col;
    float c  = sp[rr+1][col+1];
    float up = sp[rr  ][col+1], dn = sp[rr+2][col+1];
    float lf = sp[rr+1][col  ], rt = sp[rr+1][col+2];
    int gidx = (b*HP + gi)*HP + gj;
    float2 wc = g_w2[gidx];
    float wdn = wc.x, wrt = wc.y;
    float wup = (gi > 0) ? g_w2[gidx-HP].x : 0.f;
    float wlf = (gj > 0) ? g_w2[gidx-1].y  : 0.f;
    pc[kk]  = c;
    lap[kk] = (wup+wdn+wlf+wrt)*c - (wup*up + wdn*dn + wlf*lf + wrt*rt);
    float v = c;
    v += __shfl_down_sync(0xffffffffu, v, 4);
    v += __shfl_down_sync(0xffffffffu, v, 2);
    v += __shfl_down_sync(0xffffffffu, v, 1);
    if ((col & 7) == 0) atomicAdd(&scell[kk][col>>3], v);
  }
  __syncthreads();

  float d1 = 0.f, d2 = 0.f;
  #pragma unroll
  for (int kk = 0; kk < 4; kk++){
    int rr = rb_ + 8*kk;
    int gi = ty0 + rr, gj = tx0 + col;
    int cy = blockIdx.y*4 + kk, cx = blockIdx.x*4 + (col>>3);
    float m  = mask[b*1024 + cy*32 + cx];
    float Av = lap[kk] + lam*m*scell[kk][col>>3]*(1.f/4096.f);
    float sv = WS ? ssrc[rr+1][col+1] : 0.f;
    float pv = WS ? psrc[rr+1][col+1] : 0.f;
    Out_b[gi*HP + gj] = make_float4(pc[kk], Av, sv, pv);
    d1 += pc[kk]*pc[kk];
    d2 += pc[kk]*Av;
  }
  #pragma unroll
  for (int o = 16; o; o >>= 1){
    d1 += __shfl_down_sync(0xffffffffu, d1, o);
    d2 += __shfl_down_sync(0xffffffffu, d2, o);
  }
  if (col == 0){ sred[rb_] = d1; sred2[rb_] = d2; }
  __syncthreads();
  if (tid == 0){
    float s1 = 0.f, s2 = 0.f;
    #pragma unroll
    for (int i = 0; i < 8; i++){ s1 += sred[i]; s2 += sred2[i]; }
    if (i1 >= 0) atomicAdd(&g_scal[i1], s1);
    atomicAdd(&g_scal[i2], s2);
  }
}

// CG init: r0 = b - A x0, X = x0; write (r0,0,0,0) into RWS1; reduce gamma0, <b,b>
__global__ void __launch_bounds__(256) cg_init_kernel(
    const float* __restrict__ x0, const float* __restrict__ source,
    const float* __restrict__ mask, float* __restrict__ X,
    float4* __restrict__ Rinit, const float* __restrict__ loglam)
{
  const float lam = expf(loglam[0]);
  __shared__ float sp[34][36];
  __shared__ float scell[4][4];
  __shared__ float sred[8], sred2[8];
  const int b = blockIdx.z;
  const int tx0 = blockIdx.x*32, ty0 = blockIdx.y*32;
  const float* vb = x0 + (size_t)b*HW;
  for (int idx = threadIdx.x; idx < 34*34; idx += 256){
    int yy = idx/34, xx = idx - yy*34;
    int gy = ty0+yy-1, gx = tx0+xx-1;
    float v = 0.f;
    if (gy >= 0 && gy < HP && gx >= 0 && gx < HP) v = vb[gy*HP+gx];
    sp[yy][xx] = v;
  }
  if (threadIdx.x < 16) ((float*)scell)[threadIdx.x] = 0.f;
  __syncthreads();

  const int col = threadIdx.x & 31, rb_ = threadIdx.x >> 5;
  float pc[4], lap[4];
  #pragma unroll
  for (int kk = 0; kk < 4; kk++){
    int rr = rb_ + 8*kk;
    int gi = ty0 + rr, gj = tx0 + col;
    float c  = sp[rr+1][col+1];
    float up = sp[rr  ][col+1], dn = sp[rr+2][col+1];
    float lf = sp[rr+1][col  ], rt = sp[rr+1][col+2];
    int gidx = (b*HP + gi)*HP + gj;
    float2 wc = g_w2[gidx];
    float wdn = wc.x, wrt = wc.y;
    float wup = (gi > 0) ? g_w2[gidx-HP].x : 0.f;
    float wlf = (gj > 0) ? g_w2[gidx-1].y  : 0.f;
    pc[kk]  = c;
    lap[kk] = (wup+wdn+wlf+wrt)*c - (wup*up + wdn*dn + wlf*lf + wrt*rt);
    float v = c;
    v += __shfl_down_sync(0xffffffffu, v, 4);
    v += __shfl_down_sync(0xffffffffu, v, 2);
    v += __shfl_down_sync(0xffffffffu, v, 1);
    if ((col & 7) == 0) atomicAdd(&scell[kk][col>>3], v);
  }
  __syncthreads();

  float d1 = 0.f, d2 = 0.f;
  #pragma unroll
  for (int kk = 0; kk < 4; kk++){
    int rr = rb_ + 8*kk;
    int gi = ty0 + rr, gj = tx0 + col;
    int cy = blockIdx.y*4 + kk, cx = blockIdx.x*4 + (col>>3);
    float m  = mask[b*1024 + cy*32 + cx];
    float Av = lap[kk] + lam*m*scell[kk][col>>3]*(1.f/4096.f);
    int gidx = (b*HP + gi)*HP + gj;
    float bv = lam*m*source[b*1024 + cy*32 + cx]*(1.f/64.f);
    float rv = bv - Av;
    Rinit[gidx] = make_float4(rv, 0.f, 0.f, 0.f);
    X[gidx] = pc[kk];
    d1 += rv*rv; d2 += bv*bv;
  }
  #pragma unroll
  for (int o = 16; o; o >>= 1){
    d1 += __shfl_down_sync(0xffffffffu, d1, o);
    d2 += __shfl_down_sync(0xffffffffu, d2, o);
  }
  if (col == 0){ sred[rb_] = d1; sred2[rb_] = d2; }
  __syncthreads();
  if (threadIdx.x == 0){
    float s1 = 0.f, s2 = 0.f;
    #pragma unroll
    for (int i = 0; i < 8; i++){ s1 += sred[i]; s2 += sred2[i]; }
    atomicAdd(&g_scal[GAM+0], s1);
    atomicAdd(&g_scal[BBIDX], s2);
  }
}

__global__ void finalize_kernel(){
  if (threadIdx.x == 0) g_scal[ATOL2] = 1e-12f * g_scal[BBIDX];
}

// init2: w0 = A r0; write RWS0 = (r0, w0, 0, 0); reduce delta0 = <r0,w0>
__global__ void __launch_bounds__(256) cg_init2_kernel(
    const float4* __restrict__ Rinit, float4* __restrict__ Out,
    const float* __restrict__ mask, const float* __restrict__ loglam)
{
  const float lam = expf(loglam[0]);
  __shared__ float sp[34][36];
  const int b = blockIdx.z;
  const int tx0 = blockIdx.x*32, ty0 = blockIdx.y*32;
  const float4* vb = Rinit + (size_t)b*HW;
  for (int idx = threadIdx.x; idx < 34*34; idx += 256){
    int yy = idx/34, xx = idx - yy*34;
    int gy = ty0+yy-1, gx = tx0+xx-1;
    float v = 0.f;
    if (gy >= 0 && gy < HP && gx >= 0 && gx < HP) v = vb[gy*HP+gx].x;
    sp[yy][xx] = v;
  }
  matvec_phase2<false>(sp, sp, sp, lam, mask, b, tx0, ty0, Out + (size_t)b*HW, -1, DEL+0);
}

// Chronopoulos–Gear single-kernel CG iteration, float4 (r,w,s,p) in/out
__global__ void __launch_bounds__(256) cgcg_iter_kernel(
    const float4* __restrict__ In, float4* __restrict__ Out,
    float* __restrict__ X,
    const float* __restrict__ mask, int k, const float* __restrict__ loglam)
{
  float gam = g_scal[GAM+k];
  if (!(gam > g_scal[ATOL2])) return;
  float beta, alpha;
  if (k == 0){
    beta = 0.f; alpha = gam / g_scal[DEL+0];
  } else {
    beta = gam / g_scal[GAM+k-1];
    alpha = gam / (g_scal[DEL+k] - beta*gam/g_scal[ALF+k-1]);
  }
  if (threadIdx.x == 0) g_scal[ALF+k] = alpha;

  const float lam = expf(loglam[0]);
  __shared__ float sp[34][36];
  __shared__ float ssm[34][36];
  __shared__ float spp[34][36];
  const int b = blockIdx.z;
  const int tx0 = blockIdx.x*32, ty0 = blockIdx.y*32;
  const size_t boff = (size_t)b*HW;
  const float4* Ib = In + boff;
  float* Xp = X + boff;

  for (int idx = threadIdx.x; idx < 34*34; idx += 256){
    int yy = idx/34, xx = idx - yy*34;
    int gy = ty0+yy-1, gx = tx0+xx-1;
    float rn = 0.f, s = 0.f, pn = 0.f;
    if (gy >= 0 && gy < HP && gx >= 0 && gx < HP){
      int o = gy*HP+gx;
      float4 v = Ib[o];
      float rr = v.x;
      s  = (k == 0) ? v.y : fmaf(beta, v.z, v.y);
      rn = fmaf(-alpha, s, rr);
      if (yy >= 1 && yy <= 32 && xx >= 1 && xx <= 32){
        pn = (k == 0) ? rr : fmaf(beta, v.w, rr);
        Xp[o] = fmaf(alpha, pn, Xp[o]);
      }
    }
    sp[yy][xx]  = rn;
    ssm[yy][xx] = s;
    spp[yy][xx] = pn;
  }
  matvec_phase2<true>(sp, ssm, spp, lam, mask, b, tx0, ty0, Out + boff, GAM+k+1, DEL+k+1);
}

// ---------------- host orchestration ----------------
extern "C" void kernel_launch(void* const* d_in, const int* in_sizes, int n_in,
                              void* d_out, int out_size)
{
  const float* guide  = (const float*)d_in[0];
  const float* source = (const float*)d_in[1];
  const float* mask   = (const float*)d_in[2];
  const float* ybic   = (const float*)d_in[3];
  const float* gw1 = (const float*)d_in[4];  const float* gb1 = (const float*)d_in[5];
  const float* gw2 = (const float*)d_in[6];  const float* gb2 = (const float*)d_in[7];
  const float* sw1 = (const float*)d_in[8];  const float* sb1 = (const float*)d_in[9];
  const float* sw2 = (const float*)d_in[10]; const float* sb2 = (const float*)d_in[11];
  const float* vw1 = (const float*)d_in[12]; const float* vb1 = (const float*)d_in[13];
  const float* vw2 = (const float*)d_in[14]; const float* vb2 = (const float*)d_in[15];
  const float* vw3 = (const float*)d_in[16]; const float* vb3 = (const float*)d_in[17];
  const float* loglam = (const float*)d_in[18];
  const float* logmu  = (const float*)d_in[19];

  float* out  = (float*)d_out;
  float* xout = out;
  float* var  = out + (size_t)NTOT;
  float* aff  = out + (size_t)2*NTOT;

  float *h1p, *h2p, *h3p, *stg2, *stg1;
  float4 *rws0, *rws1;
  cudaGetSymbolAddress((void**)&h1p, g_h1);
  cudaGetSymbolAddress((void**)&h2p, g_h2);
  cudaGetSymbolAddress((void**)&h3p, g_h3);
  cudaGetSymbolAddress((void**)&rws0, g_RWS0);
  cudaGetSymbolAddress((void**)&rws1, g_RWS1);
  cudaGetSymbolAddress((void**)&stg2, g_w2t_stage);
  cudaGetSymbolAddress((void**)&stg1, g_w1t_stage);

  auto fsz = [](int cin){ return (size_t)(cin*20*21 + 32*18*20)*4; };
  cudaFuncSetAttribute(conv3x3_fused2<3,1,true >, cudaFuncAttributeMaxDynamicSharedMemorySize, (int)fsz(4));
  cudaFuncSetAttribute(conv3x3_fused2<3,0,false>, cudaFuncAttributeMaxDynamicSharedMemorySize, (int)fsz(3));
  cudaFuncSetAttribute(conv3x3_fused2<1,0,false>, cudaFuncAttributeMaxDynamicSharedMemorySize, (int)fsz(1));

  dim3 gc(16, 16, NB);    // fused conv tiles 16x16
  dim3 g1(8, 8, NB);      // 32x32 tiles
  dim3 gm(8, 8, NB);      // CG tiles 32x32

  zero_scal_kernel<<<1,256>>>();

  // variance net
  transpose_w2_kernel<<<36,256>>>(vw2);
  transpose_w1_kernel<<<5,256>>>(vw1, 4);
  cudaMemcpyToSymbolAsync(c_w2t, stg2, 9216*4, 0, cudaMemcpyDeviceToDevice, 0);
  cudaMemcpyToSymbolAsync(c_w1t, stg1, 4*9*32*4, 0, cudaMemcpyDeviceToDevice, 0);
  conv3x3_fused2<3,1,true ><<<gc,256,fsz(4)>>>(guide, ybic, vb1, vb2, h1p);
  conv3x3_one<<<g1,256>>>(h1p, vw3, vb3, var);

  // guide features
  transpose_w2_kernel<<<36,256>>>(gw2);
  transpose_w1_kernel<<<4,256>>>(gw1, 3);
  cudaMemcpyToSymbolAsync(c_w2t, stg2, 9216*4, 0, cudaMemcpyDeviceToDevice, 0);
  cudaMemcpyToSymbolAsync(c_w1t, stg1, 3*9*32*4, 0, cudaMemcpyDeviceToDevice, 0);
  conv3x3_fused2<3,0,false><<<gc,256,fsz(3)>>>(guide, nullptr, gb1, gb2, h2p);

  // source features
  transpose_w2_kernel<<<36,256>>>(sw2);
  transpose_w1_kernel<<<2,256>>>(sw1, 1);
  cudaMemcpyToSymbolAsync(c_w2t, stg2, 9216*4, 0, cudaMemcpyDeviceToDevice, 0);
  cudaMemcpyToSymbolAsync(c_w1t, stg1, 1*9*32*4, 0, cudaMemcpyDeviceToDevice, 0);
  conv3x3_fused2<1,0,false><<<gc,256,fsz(1)>>>(ybic, nullptr, sb1, sb2, h3p);

  // edge weights + aff output
  affinity_kernel<<<g1,256>>>(logmu);
  assemble_kernel<<<NTOT/256,256>>>(aff, loglam);

  // CG init: (r0,0,0,0) into RWS1; then RWS0 = (r0, A r0, 0, 0)
  cg_init_kernel<<<gm,256>>>(ybic, source, mask, xout, rws1, loglam);
  finalize_kernel<<<1,32>>>();
  cg_init2_kernel<<<gm,256>>>(rws1, rws0, mask, loglam);

  // single-kernel CG-CG iterations (ping-pong RWS with p in .w)
  for (int k = 0; k < 100; k++){
    if ((k & 1) == 0)
      cgcg_iter_kernel<<<gm,256>>>(rws0, rws1, xout, mask, k, loglam);
    else
      cgcg_iter_kernel<<<gm,256>>>(rws1, rws0, xout, mask, k, loglam);
  }
}

// round 17
// speedup vs baseline: 1.3246x; 1.3246x over previous
#include <cuda_runtime.h>
#include <math.h>

typedef unsigned long long ull;

#define NB 16
#define HP 256
#define HW 65536
#define NTOT (NB*HW)

// g_scal layout
#define GAM   0
#define DEL   110
#define ALF   220
#define BBIDX 330
#define ATOL2 331

// ---------------- static device scratch ----------------
__device__ float  g_h1[(size_t)NB*32*HW];   // variance hidden
__device__ float  g_h2[(size_t)NB*32*HW];   // g-features
__device__ float  g_h3[(size_t)NB*32*HW];   // s-features
__device__ float2 g_w2[NTOT];               // (wv, wh) packed
__device__ float4 g_RWS0[NTOT];             // (r, w=Ar, s, p) ping
__device__ float4 g_RWS1[NTOT];             // pong
__device__ float  g_scal[512];

// conv2 weights in constant memory (uniform-path loads, off the LDS crossbar)
__constant__ float c_w2t[9216];

// ---------------- f32x2 helpers ----------------
__device__ __forceinline__ ull pack2(float a, float b){ ull r; asm("mov.b64 %0, {%1, %2};" : "=l"(r) : "f"(a), "f"(b)); return r; }
__device__ __forceinline__ void ffma2(ull& d, ull a, ull b){ asm("fma.rn.f32x2 %0, %1, %2, %0;" : "+l"(d) : "l"(a), "l"(b)); }
__device__ __forceinline__ float2 unpack2(ull v){ float2 f; asm("mov.b64 {%0, %1}, %2;" : "=f"(f.x), "=f"(f.y) : "l"(v)); return f; }

__global__ void zero_scal_kernel(){ g_scal[threadIdx.x] = 0.f; g_scal[256+threadIdx.x] = 0.f; }

// transpose conv2 weights OIHW -> [(ci*9+tap)*32+co] into gmem staging buffer
__device__ float g_w2t_stage[9216];
__global__ void transpose_w2_kernel(const float* __restrict__ W2){
  int idx = blockIdx.x*256 + threadIdx.x;
  if (idx < 9216){
    int co = idx & 31; int ct = idx >> 5;
    int ci = ct/9, tap = ct - ci*9;
    g_w2t_stage[idx] = W2[((size_t)co*32 + ci)*9 + tap];
  }
}

// =====================================================================
// FUSED conv1(CIN->32, relu) + conv2(32->32, RELU2), 16x16 tile.
// conv1 weights in smem; conv2 weights in __constant__. (R10 config)
// =====================================================================
template<int CINA,int CINB,bool RELU2>
__global__ void __launch_bounds__(256,2) conv3x3_fused2(
    const float* __restrict__ inA, const float* __restrict__ inB,
    const float* __restrict__ W1, const float* __restrict__ b1,
    const float* __restrict__ b2,
    float* __restrict__ out)
{
  constexpr int CIN = CINA + CINB;
  extern __shared__ float sm[];
  float* s_in = sm;                       // CIN*20*21
  float* s_w1 = s_in + CIN*20*21;         // CIN*9*32
  float* s_h  = s_w1 + CIN*9*32;          // 32*18*20

  const int tid = threadIdx.x;
  const int b   = blockIdx.z;
  const int tx0 = blockIdx.x*16, ty0 = blockIdx.y*16;

  for (int idx = tid; idx < CIN*9*32; idx += 256){
    int co = idx & 31; int ct = idx >> 5;
    int ci = ct/9, tap = ct - ci*9;
    s_w1[idx] = W1[((size_t)co*CIN + ci)*9 + tap];
  }
  for (int idx = tid; idx < CIN*400; idx += 256){
    int ci = idx/400; int rem = idx - ci*400;
    int r = rem/20, c2 = rem - r*20;
    int gy = ty0 + r - 2, gx = tx0 + c2 - 2;
    const float* src = (ci < CINA) ? (inA + ((size_t)b*CINA + ci)*HW)
                                   : (inB + ((size_t)b*CINB + (ci-CINA))*HW);
    float v = 0.f;
    if (gy >= 0 && gy < HP && gx >= 0 && gx < HP) v = src[gy*HP+gx];
    s_in[(ci*20 + r)*21 + c2] = v;
  }
  __syncthreads();

  // ---- conv1 + relu -> s_h on 18x18 halo ----
  for (int p = tid; p < 324; p += 256){
    int yy = p/18, xx = p - yy*18;
    int gy = ty0 + yy - 1, gx = tx0 + xx - 1;
    if (gy < 0 || gy >= HP || gx < 0 || gx >= HP){
      #pragma unroll
      for (int co = 0; co < 32; co++) s_h[(co*18 + yy)*20 + xx] = 0.f;
    } else {
      ull acc[16];
      #pragma unroll
      for (int q = 0; q < 16; q++) acc[q] = pack2(__ldg(&b1[2*q]), __ldg(&b1[2*q+1]));
      #pragma unroll
      for (int ci = 0; ci < CIN; ci++){
        #pragma unroll
        for (int ky = 0; ky < 3; ky++)
          #pragma unroll
          for (int kx = 0; kx < 3; kx++){
            float v = s_in[(ci*20 + yy + ky)*21 + xx + kx];
            ull vv = pack2(v, v);
            const ull* wp = reinterpret_cast<const ull*>(s_w1 + (ci*9 + ky*3 + kx)*32);
            #pragma unroll
            for (int q = 0; q < 16; q++) ffma2(acc[q], vv, wp[q]);
          }
      }
      #pragma unroll
      for (int q = 0; q < 16; q++){
        float2 a = unpack2(acc[q]);
        a.x = fmaxf(a.x, 0.f); a.y = fmaxf(a.y, 0.f);
        s_h[((2*q  )*18 + yy)*20 + xx] = a.x;
        s_h[((2*q+1)*18 + yy)*20 + xx] = a.y;
      }
    }
  }
  __syncthreads();

  // ---- conv2 from smem inputs + constant weights (R10 register tile) ----
  const int cog  = tid >> 6;
  const int slot = tid & 63;
  const int px   = slot & 15;
  const int py   = (slot >> 4) << 2;

  ull acc[4][4];
  #pragma unroll
  for (int q = 0; q < 4; q++){
    int co0 = 2*(cog*4 + q);
    ull bz = pack2(__ldg(&b2[co0]), __ldg(&b2[co0+1]));
    #pragma unroll
    for (int pix = 0; pix < 4; pix++) acc[pix][q] = bz;
  }

  #pragma unroll 1
  for (int cl = 0; cl < 32; cl++){
    ull vp[6][3];
    #pragma unroll
    for (int dy = 0; dy < 6; dy++)
      #pragma unroll
      for (int dx = 0; dx < 3; dx++){
        float f = s_h[(cl*18 + py + dy)*20 + px + dx];
        vp[dy][dx] = pack2(f, f);
      }
    #pragma unroll
    for (int ky = 0; ky < 3; ky++)
      #pragma unroll
      for (int kx = 0; kx < 3; kx++){
        const ull* wp = reinterpret_cast<const ull*>(c_w2t + (cl*9 + ky*3 + kx)*32) + cog*4;
        #pragma unroll
        for (int q = 0; q < 4; q++){
          ull w = wp[q];
          #pragma unroll
          for (int pix = 0; pix < 4; pix++)
            ffma2(acc[pix][q], vp[pix+ky][kx], w);
        }
      }
  }

  #pragma unroll
  for (int q = 0; q < 4; q++){
    int co0 = 2*(cog*4 + q);
    #pragma unroll
    for (int pix = 0; pix < 4; pix++){
      float2 a = unpack2(acc[pix][q]);
      if (RELU2){ a.x = fmaxf(a.x, 0.f); a.y = fmaxf(a.y, 0.f); }
      size_t o = ((size_t)b*32 + co0)*HW + (size_t)(ty0+py+pix)*HP + (tx0+px);
      out[o] = a.x; out[o + HW] = a.y;
    }
  }
}

// conv 32 -> 1 (variance head)
__global__ void __launch_bounds__(256) conv3x3_one(
    const float* __restrict__ in, const float* __restrict__ W,
    const float* __restrict__ bias, float* __restrict__ out)
{
  __shared__ float s_in[8][34][36];
  __shared__ float s_w[8*9];
  const int tid = threadIdx.x;
  const int px = tid & 31;
  const int py = (tid >> 5) << 2;
  const int b = blockIdx.z;
  const int tx0 = blockIdx.x*32, ty0 = blockIdx.y*32;

  float acc[4];
  float bz = __ldg(&bias[0]);
  #pragma unroll
  for (int pix = 0; pix < 4; pix++) acc[pix] = bz;

  #pragma unroll 1
  for (int c0 = 0; c0 < 32; c0 += 8){
    if (c0) __syncthreads();
    if (tid < 72) s_w[tid] = W[c0*9 + tid];
    for (int idx = tid; idx < 8*1156; idx += 256){
      int cl = idx/1156; int rem = idx - cl*1156;
      int yy = rem/34, xx = rem - yy*34;
      int gy = ty0+yy-1, gx = tx0+xx-1;
      float v = 0.f;
      if (gy >= 0 && gy < HP && gx >= 0 && gx < HP)
        v = in[((size_t)b*32 + c0+cl)*HW + gy*HP + gx];
      s_in[cl][yy][xx] = v;
    }
    __syncthreads();
    #pragma unroll 1
    for (int cl = 0; cl < 8; cl++){
      float v[6][3];
      #pragma unroll
      for (int dy = 0; dy < 6; dy++)
        #pragma unroll
        for (int dx = 0; dx < 3; dx++) v[dy][dx] = s_in[cl][py+dy][px+dx];
      #pragma unroll
      for (int ky = 0; ky < 3; ky++)
        #pragma unroll
        for (int kx = 0; kx < 3; kx++){
          float w = s_w[cl*9 + ky*3 + kx];
          #pragma unroll
          for (int pix = 0; pix < 4; pix++) acc[pix] += v[pix+ky][kx]*w;
        }
    }
  }
  #pragma unroll
  for (int pix = 0; pix < 4; pix++)
    out[(size_t)b*HW + (size_t)(ty0+py+pix)*HP + (tx0+px)] = acc[pix];
}

// ---------------- affinity (smem-tiled), writes packed float2 (wv,wh) ----------------
__global__ void __launch_bounds__(256) affinity_kernel(const float* __restrict__ logmu){
  __shared__ float sg[33][36], ss[33][36];
  const int b = blockIdx.z, tx0 = blockIdx.x*32, ty0 = blockIdx.y*32;
  const float mu = expf(logmu[0]);
  const int px = threadIdx.x & 31, py = (threadIdx.x >> 5) << 2;
  float dv[4] = {0,0,0,0}, dh[4] = {0,0,0,0};
  const float* gb = g_h2 + (size_t)b*32*HW;
  const float* sb = g_h3 + (size_t)b*32*HW;

  #pragma unroll 1
  for (int c = 0; c < 32; c++){
    __syncthreads();
    for (int idx = threadIdx.x; idx < 33*33; idx += 256){
      int yy = idx/33, xx = idx - yy*33;
      int gy = ty0+yy, gx = tx0+xx;
      float vg = 0.f, vs = 0.f;
      if (gy < HP && gx < HP){
        size_t o = (size_t)c*HW + gy*HP + gx;
        vg = gb[o]; vs = sb[o];
      }
      sg[yy][xx] = vg; ss[yy][xx] = vs;
    }
    __syncthreads();
    #pragma unroll
    for (int k = 0; k < 4; k++){
      int y = py + k;
      float a  = sg[y][px], a2 = ss[y][px];
      float d;
      d = sg[y+1][px]   - a;  dv[k] += d*d;
      d = ss[y+1][px]   - a2; dv[k] += d*d;
      d = sg[y][px+1]   - a;  dh[k] += d*d;
      d = ss[y][px+1]   - a2; dh[k] += d*d;
    }
  }
  #pragma unroll
  for (int k = 0; k < 4; k++){
    int gi = ty0+py+k, gj = tx0+px;
    int idx = (b*HP + gi)*HP + gj;
    float wv = (gi < 255) ? expf(-mu*dv[k]) : 0.f;
    float wh = (gj < 255) ? expf(-mu*dh[k]) : 0.f;
    g_w2[idx] = make_float2(wv, wh);
  }
}

// ---------------- assemble aff output (B,5,H,W) ----------------
__global__ void __launch_bounds__(256) assemble_kernel(float* __restrict__ aff, const float* __restrict__ loglam){
  int idx = blockIdx.x*256 + threadIdx.x;
  int b = idx >> 16, rem = idx & 65535, i = rem >> 8, j = rem & 255;
  float lam = expf(loglam[0]);
  float2 c = g_w2[idx];
  float wdn = c.x, wrt = c.y;
  float wup = (i > 0) ? g_w2[idx-HP].x : 0.f;
  float wlf = (j > 0) ? g_w2[idx-1].y  : 0.f;
  float* o = aff + (size_t)b*5*HW + rem;
  o[0]            = wup;
  o[HW]           = wdn;
  o[(size_t)2*HW] = wlf;
  o[(size_t)3*HW] = wrt;
  o[(size_t)4*HW] = wup + wdn + wlf + wrt + lam;
}

// ======================= CG on 32x32 tiles, float4 (r,w,s,p) =======================
template<bool WS>
__device__ __forceinline__ void matvec_phase2(
    float sp[34][36], const float ssrc[34][36], const float psrc[34][36],
    float lam, const float* __restrict__ mask,
    int b, int tx0, int ty0, float4* __restrict__ Out_b, int i1, int i2)
{
  __shared__ float scell[4][4];
  __shared__ float sred[8], sred2[8];
  const int tid = threadIdx.x;
  if (tid < 16) ((float*)scell)[tid] = 0.f;
  __syncthreads();

  const int col = tid & 31, rb_ = tid >> 5;
  float pc[4], lap[4];
  #pragma unroll
  for (int kk = 0; kk < 4; kk++){
    int rr = rb_ + 8*kk;
    int gi = ty0 + rr, gj = tx0 + col;
    float c  = sp[rr+1][col+1];
    float up = sp[rr  ][col+1], dn = sp[rr+2][col+1];
    float lf = sp[rr+1][col  ], rt = sp[rr+1][col+2];
    int gidx = (b*HP + gi)*HP + gj;
    float2 wc = g_w2[gidx];
    float wdn = wc.x, wrt = wc.y;
    float wup = (gi > 0) ? g_w2[gidx-HP].x : 0.f;
    float wlf = (gj > 0) ? g_w2[gidx-1].y  : 0.f;
    pc[kk]  = c;
    lap[kk] = (wup+wdn+wlf+wrt)*c - (wup*up + wdn*dn + wlf*lf + wrt*rt);
    float v = c;
    v += __shfl_down_sync(0xffffffffu, v, 4);
    v += __shfl_down_sync(0xffffffffu, v, 2);
    v += __shfl_down_sync(0xffffffffu, v, 1);
    if ((col & 7) == 0) atomicAdd(&scell[kk][col>>3], v);
  }
  __syncthreads();

  float d1 = 0.f, d2 = 0.f;
  #pragma unroll
  for (int kk = 0; kk < 4; kk++){
    int rr = rb_ + 8*kk;
    int gi = ty0 + rr, gj = tx0 + col;
    int cy = blockIdx.y*4 + kk, cx = blockIdx.x*4 + (col>>3);
    float m  = mask[b*1024 + cy*32 + cx];
    float Av = lap[kk] + lam*m*scell[kk][col>>3]*(1.f/4096.f);
    float sv = WS ? ssrc[rr+1][col+1] : 0.f;
    float pv = WS ? psrc[rr+1][col+1] : 0.f;
    Out_b[gi*HP + gj] = make_float4(pc[kk], Av, sv, pv);
    d1 += pc[kk]*pc[kk];
    d2 += pc[kk]*Av;
  }
  #pragma unroll
  for (int o = 16; o; o >>= 1){
    d1 += __shfl_down_sync(0xffffffffu, d1, o);
    d2 += __shfl_down_sync(0xffffffffu, d2, o);
  }
  if (col == 0){ sred[rb_] = d1; sred2[rb_] = d2; }
  __syncthreads();
  if (tid == 0){
    float s1 = 0.f, s2 = 0.f;
    #pragma unroll
    for (int i = 0; i < 8; i++){ s1 += sred[i]; s2 += sred2[i]; }
    if (i1 >= 0) atomicAdd(&g_scal[i1], s1);
    atomicAdd(&g_scal[i2], s2);
  }
}

// CG init: r0 = b - A x0, X = x0; write (r0,0,0,0) into RWS1; reduce gamma0, <b,b>
__global__ void __launch_bounds__(256) cg_init_kernel(
    const float* __restrict__ x0, const float* __restrict__ source,
    const float* __restrict__ mask, float* __restrict__ X,
    float4* __restrict__ Rinit, const float* __restrict__ loglam)
{
  const float lam = expf(loglam[0]);
  __shared__ float sp[34][36];
  __shared__ float scell[4][4];
  __shared__ float sred[8], sred2[8];
  const int b = blockIdx.z;
  const int tx0 = blockIdx.x*32, ty0 = blockIdx.y*32;
  const float* vb = x0 + (size_t)b*HW;
  for (int idx = threadIdx.x; idx < 34*34; idx += 256){
    int yy = idx/34, xx = idx - yy*34;
    int gy = ty0+yy-1, gx = tx0+xx-1;
    float v = 0.f;
    if (gy >= 0 && gy < HP && gx >= 0 && gx < HP) v = vb[gy*HP+gx];
    sp[yy][xx] = v;
  }
  if (threadIdx.x < 16) ((float*)scell)[threadIdx.x] = 0.f;
  __syncthreads();

  const int col = threadIdx.x & 31, rb_ = threadIdx.x >> 5;
  float pc[4], lap[4];
  #pragma unroll
  for (int kk = 0; kk < 4; kk++){
    int rr = rb_ + 8*kk;
    int gi = ty0 + rr, gj = tx0 + col;
    float c  = sp[rr+1][col+1];
    float up = sp[rr  ][col+1], dn = sp[rr+2][col+1];
    float lf = sp[rr+1][col  ], rt = sp[rr+1][col+2];
    int gidx = (b*HP + gi)*HP + gj;
    float2 wc = g_w2[gidx];
    float wdn = wc.x, wrt = wc.y;
    float wup = (gi > 0) ? g_w2[gidx-HP].x : 0.f;
    float wlf = (gj > 0) ? g_w2[gidx-1].y  : 0.f;
    pc[kk]  = c;
    lap[kk] = (wup+wdn+wlf+wrt)*c - (wup*up + wdn*dn + wlf*lf + wrt*rt);
    float v = c;
    v += __shfl_down_sync(0xffffffffu, v, 4);
    v += __shfl_down_sync(0xffffffffu, v, 2);
    v += __shfl_down_sync(0xffffffffu, v, 1);
    if ((col & 7) == 0) atomicAdd(&scell[kk][col>>3], v);
  }
  __syncthreads();

  float d1 = 0.f, d2 = 0.f;
  #pragma unroll
  for (int kk = 0; kk < 4; kk++){
    int rr = rb_ + 8*kk;
    int gi = ty0 + rr, gj = tx0 + col;
    int cy = blockIdx.y*4 + kk, cx = blockIdx.x*4 + (col>>3);
    float m  = mask[b*1024 + cy*32 + cx];
    float Av = lap[kk] + lam*m*scell[kk][col>>3]*(1.f/4096.f);
    int gidx = (b*HP + gi)*HP + gj;
    float bv = lam*m*source[b*1024 + cy*32 + cx]*(1.f/64.f);
    float rv = bv - Av;
    Rinit[gidx] = make_float4(rv, 0.f, 0.f, 0.f);
    X[gidx] = pc[kk];
    d1 += rv*rv; d2 += bv*bv;
  }
  #pragma unroll
  for (int o = 16; o; o >>= 1){
    d1 += __shfl_down_sync(0xffffffffu, d1, o);
    d2 += __shfl_down_sync(0xffffffffu, d2, o);
  }
  if (col == 0){ sred[rb_] = d1; sred2[rb_] = d2; }
  __syncthreads();
  if (threadIdx.x == 0){
    float s1 = 0.f, s2 = 0.f;
    #pragma unroll
    for (int i = 0; i < 8; i++){ s1 += sred[i]; s2 += sred2[i]; }
    atomicAdd(&g_scal[GAM+0], s1);
    atomicAdd(&g_scal[BBIDX], s2);
  }
}

__global__ void finalize_kernel(){
  if (threadIdx.x == 0) g_scal[ATOL2] = 1e-12f * g_scal[BBIDX];
}

// init2: w0 = A r0; write RWS0 = (r0, w0, 0, 0); reduce delta0 = <r0,w0>
__global__ void __launch_bounds__(256) cg_init2_kernel(
    const float4* __restrict__ Rinit, float4* __restrict__ Out,
    const float* __restrict__ mask, const float* __restrict__ loglam)
{
  const float lam = expf(loglam[0]);
  __shared__ float sp[34][36];
  const int b = blockIdx.z;
  const int tx0 = blockIdx.x*32, ty0 = blockIdx.y*32;
  const float4* vb = Rinit + (size_t)b*HW;
  for (int idx = threadIdx.x; idx < 34*34; idx += 256){
    int yy = idx/34, xx = idx - yy*34;
    int gy = ty0+yy-1, gx = tx0+xx-1;
    float v = 0.f;
    if (gy >= 0 && gy < HP && gx >= 0 && gx < HP) v = vb[gy*HP+gx].x;
    sp[yy][xx] = v;
  }
  matvec_phase2<false>(sp, sp, sp, lam, mask, b, tx0, ty0, Out + (size_t)b*HW, -1, DEL+0);
}

// Chronopoulos–Gear single-kernel CG iteration, float4 (r,w,s,p) in/out
__global__ void __launch_bounds__(256) cgcg_iter_kernel(
    const float4* __restrict__ In, float4* __restrict__ Out,
    float* __restrict__ X,
    const float* __restrict__ mask, int k, const float* __restrict__ loglam)
{
  float gam = g_scal[GAM+k];
  if (!(gam > g_scal[ATOL2])) return;
  float beta, alpha;
  if (k == 0){
    beta = 0.f; alpha = gam / g_scal[DEL+0];
  } else {
    beta = gam / g_scal[GAM+k-1];
    alpha = gam / (g_scal[DEL+k] - beta*gam/g_scal[ALF+k-1]);
  }
  if (threadIdx.x == 0) g_scal[ALF+k] = alpha;

  const float lam = expf(loglam[0]);
  __shared__ float sp[34][36];
  __shared__ float ssm[34][36];
  __shared__ float spp[34][36];
  const int b = blockIdx.z;
  const int tx0 = blockIdx.x*32, ty0 = blockIdx.y*32;
  const size_t boff = (size_t)b*HW;
  const float4* Ib = In + boff;
  float* Xp = X + boff;

  for (int idx = threadIdx.x; idx < 34*34; idx += 256){
    int yy = idx/34, xx = idx - yy*34;
    int gy = ty0+yy-1, gx = tx0+xx-1;
    float rn = 0.f, s = 0.f, pn = 0.f;
    if (gy >= 0 && gy < HP && gx >= 0 && gx < HP){
      int o = gy*HP+gx;
      float4 v = Ib[o];
      float rr = v.x;
      s  = (k == 0) ? v.y : fmaf(beta, v.z, v.y);
      rn = fmaf(-alpha, s, rr);
      if (yy >= 1 && yy <= 32 && xx >= 1 && xx <= 32){
        pn = (k == 0) ? rr : fmaf(beta, v.w, rr);
        Xp[o] = fmaf(alpha, pn, Xp[o]);
      }
    }
    sp[yy][xx]  = rn;
    ssm[yy][xx] = s;
    spp[yy][xx] = pn;
  }
  matvec_phase2<true>(sp, ssm, spp, lam, mask, b, tx0, ty0, Out + boff, GAM+k+1, DEL+k+1);
}

// ---------------- host orchestration ----------------
extern "C" void kernel_launch(void* const* d_in, const int* in_sizes, int n_in,
                              void* d_out, int out_size)
{
  const float* guide  = (const float*)d_in[0];
  const float* source = (const float*)d_in[1];
  const float* mask   = (const float*)d_in[2];
  const float* ybic   = (const float*)d_in[3];
  const float* gw1 = (const float*)d_in[4];  const float* gb1 = (const float*)d_in[5];
  const float* gw2 = (const float*)d_in[6];  const float* gb2 = (const float*)d_in[7];
  const float* sw1 = (const float*)d_in[8];  const float* sb1 = (const float*)d_in[9];
  const float* sw2 = (const float*)d_in[10]; const float* sb2 = (const float*)d_in[11];
  const float* vw1 = (const float*)d_in[12]; const float* vb1 = (const float*)d_in[13];
  const float* vw2 = (const float*)d_in[14]; const float* vb2 = (const float*)d_in[15];
  const float* vw3 = (const float*)d_in[16]; const float* vb3 = (const float*)d_in[17];
  const float* loglam = (const float*)d_in[18];
  const float* logmu  = (const float*)d_in[19];

  float* out  = (float*)d_out;
  float* xout = out;
  float* var  = out + (size_t)NTOT;
  float* aff  = out + (size_t)2*NTOT;

  float *h1p, *h2p, *h3p, *stg2;
  float4 *rws0, *rws1;
  cudaGetSymbolAddress((void**)&h1p, g_h1);
  cudaGetSymbolAddress((void**)&h2p, g_h2);
  cudaGetSymbolAddress((void**)&h3p, g_h3);
  cudaGetSymbolAddress((void**)&rws0, g_RWS0);
  cudaGetSymbolAddress((void**)&rws1, g_RWS1);
  cudaGetSymbolAddress((void**)&stg2, g_w2t_stage);

  auto fsz = [](int cin){ return (size_t)(cin*20*21 + cin*9*32 + 32*18*20)*4; };
  cudaFuncSetAttribute(conv3x3_fused2<3,1,true >, cudaFuncAttributeMaxDynamicSharedMemorySize, (int)fsz(4));
  cudaFuncSetAttribute(conv3x3_fused2<3,0,false>, cudaFuncAttributeMaxDynamicSharedMemorySize, (int)fsz(3));
  cudaFuncSetAttribute(conv3x3_fused2<1,0,false>, cudaFuncAttributeMaxDynamicSharedMemorySize, (int)fsz(1));

  dim3 gc(16, 16, NB);    // fused conv tiles 16x16
  dim3 g1(8, 8, NB);      // 32x32 tiles
  dim3 gm(8, 8, NB);      // CG tiles 32x32

  zero_scal_kernel<<<1,256>>>();

  // variance net: stage vw2 -> const, fused conv1+conv2, then 32->1
  transpose_w2_kernel<<<36,256>>>(vw2);
  cudaMemcpyToSymbolAsync(c_w2t, stg2, 9216*4, 0, cudaMemcpyDeviceToDevice, 0);
  conv3x3_fused2<3,1,true ><<<gc,256,fsz(4)>>>(guide, ybic, vw1, vb1, vb2, h1p);
  conv3x3_one<<<g1,256>>>(h1p, vw3, vb3, var);

  // guide features
  transpose_w2_kernel<<<36,256>>>(gw2);
  cudaMemcpyToSymbolAsync(c_w2t, stg2, 9216*4, 0, cudaMemcpyDeviceToDevice, 0);
  conv3x3_fused2<3,0,false><<<gc,256,fsz(3)>>>(guide, nullptr, gw1, gb1, gb2, h2p);

  // source features
  transpose_w2_kernel<<<36,256>>>(sw2);
  cudaMemcpyToSymbolAsync(c_w2t, stg2, 9216*4, 0, cudaMemcpyDeviceToDevice, 0);
  conv3x3_fused2<1,0,false><<<gc,256,fsz(1)>>>(ybic, nullptr, sw1, sb1, sb2, h3p);

  // edge weights + aff output
  affinity_kernel<<<g1,256>>>(logmu);
  assemble_kernel<<<NTOT/256,256>>>(aff, loglam);

  // CG init: (r0,0,0,0) into RWS1; then RWS0 = (r0, A r0, 0, 0)
  cg_init_kernel<<<gm,256>>>(ybic, source, mask, xout, rws1, loglam);
  finalize_kernel<<<1,32>>>();
  cg_init2_kernel<<<gm,256>>>(rws1, rws0, mask, loglam);

  // single-kernel CG-CG iterations (ping-pong RWS with p in .w)
  for (int k = 0; k < 100; k++){
    if ((k & 1) == 0)
      cgcg_iter_kernel<<<gm,256>>>(rws0, rws1, xout, mask, k, loglam);
    else
      cgcg_iter_kernel<<<gm,256>>>(rws1, rws0, xout, mask, k, loglam);
  }
}